// round 13
// baseline (speedup 1.0000x reference)
#include <cuda_runtime.h>
#include <cuda_fp16.h>
#include <stdint.h>

// Problem constants
#define BB 32
#define CC_ 256
#define OO 256
#define HH 56
#define WW 56
#define CHK 4
#define HW (HH*WW)          // 3136

// ---------------- scratch (device globals: allocation-free) ----------------
__device__ float g_pooled[BB*CC_];
__device__ float g_h[BB*CC_];
__device__ float g_kern[BB*CC_*CHK];
// x transposed+converted: [b][px][c] fp16
__device__ __align__(16) __half g_xh[(size_t)BB*HW*CC_];
// dyn weights fp16: [b][tap(9)][oc(256)][c(256)], stored as uint32 c-pairs
__device__ __align__(16) uint32_t g_w[(size_t)BB*9*OO*(CC_/2)];

// ---------------- PTX helpers ----------------
__device__ __forceinline__ uint32_t smem_u32(const void* p) {
    uint32_t a;
    asm("{ .reg .u64 t; cvta.to.shared.u64 t, %1; cvt.u32.u64 %0, t; }" : "=r"(a) : "l"(p));
    return a;
}
__device__ __forceinline__ void cp_async16(uint32_t dst, const void* src) {
    asm volatile("cp.async.ca.shared.global [%0], [%1], 16;" :: "r"(dst), "l"(src));
}
__device__ __forceinline__ void st_smem_zero16(uint32_t dst) {
    asm volatile("st.shared.v4.u32 [%0], {%1,%1,%1,%1};" :: "r"(dst), "r"(0u));
}
__device__ __forceinline__ void ldm4(uint32_t* r, uint32_t addr) {
    asm volatile("ldmatrix.sync.aligned.m8n8.x4.shared.b16 {%0,%1,%2,%3}, [%4];"
                 : "=r"(r[0]), "=r"(r[1]), "=r"(r[2]), "=r"(r[3]) : "r"(addr));
}
__device__ __forceinline__ void mma16816(float* d, const uint32_t* a, uint32_t b0, uint32_t b1) {
    asm volatile("mma.sync.aligned.m16n8k16.row.col.f32.f16.f16.f32 "
                 "{%0,%1,%2,%3}, {%4,%5,%6,%7}, {%8,%9}, {%0,%1,%2,%3};"
                 : "+f"(d[0]), "+f"(d[1]), "+f"(d[2]), "+f"(d[3])
                 : "r"(a[0]), "r"(a[1]), "r"(a[2]), "r"(a[3]), "r"(b0), "r"(b1));
}

// ---------------- kernel 1: global average pool ----------------
__global__ __launch_bounds__(128) void pool_kernel(const float* __restrict__ x) {
    int bc = blockIdx.x;
    const float4* xp = (const float4*)(x + (size_t)bc * HW);
    float s = 0.f;
    for (int i = threadIdx.x; i < HW/4; i += 128) {
        float4 v = xp[i];
        s += (v.x + v.y) + (v.z + v.w);
    }
    for (int off = 16; off > 0; off >>= 1)
        s += __shfl_down_sync(0xffffffffu, s, off);
    __shared__ float red[4];
    if ((threadIdx.x & 31) == 0) red[threadIdx.x >> 5] = s;
    __syncthreads();
    if (threadIdx.x == 0) {
        float t = red[0] + red[1] + red[2] + red[3];
        g_pooled[bc] = t * (1.0f / (float)HW);
    }
}

// ---------------- kernel 2: fused fc1 (relu) + fc2 ----------------
__global__ __launch_bounds__(1024) void fc12_kernel(const float* __restrict__ fc1_w,
                                                    const float* __restrict__ fc2_w,
                                                    const float* __restrict__ fc2_b) {
    int b = blockIdx.x;
    int j = threadIdx.x;                 // 0..1023
    __shared__ float sp[CC_];
    __shared__ float sh[CC_];
    if (j < CC_) sp[j] = g_pooled[b*CC_ + j];
    __syncthreads();
    if (j < CC_) {
        const float* wr = fc1_w + (size_t)j * CC_;
        float s = 0.f;
        #pragma unroll 8
        for (int k = 0; k < CC_; ++k) s = fmaf(sp[k], wr[k], s);
        sh[j] = fmaxf(s, 0.f);
    }
    __syncthreads();
    const float* wr = fc2_w + (size_t)j * CC_;
    float s = fc2_b[j];
    #pragma unroll 8
    for (int k = 0; k < CC_; ++k) s = fmaf(sh[k], wr[k], s);
    g_kern[b*(CC_*CHK) + j] = s;
}

// ---------------- kernel 3: COMBO = xcvt (x->fp16 transposed) + dynw ----------------
#define XCVT_BLOCKS (49*4*BB)            // 6272
#define DYNW_BLOCKS ((BB*9*OO*(CC_/2))/256)  // 36864

__global__ __launch_bounds__(256) void combo_kernel(const float* __restrict__ x,
                                                    const float* __restrict__ cog,
                                                    const float* __restrict__ weight) {
    __shared__ __half t[64][72];
    const int bid = blockIdx.x;
    const int tid = threadIdx.x;

    if (bid < XCVT_BLOCKS) {
        // ---- xcvt part: fp32 [b][c][hw] -> fp16 [b][hw][c] ----
        const int pxt = (bid % 49) * 64;
        const int ct  = ((bid / 49) & 3) * 64;
        const int b   = bid / (49*4);

        int cl = tid >> 2;               // 0..63
        int pg = tid & 3;                // 0..3  (16 px each)
        const float4* src = (const float4*)(x + ((size_t)(b*CC_ + ct + cl)*HW + pxt + pg*16));
        #pragma unroll
        for (int u = 0; u < 4; ++u) {
            float4 v = src[u];
            t[cl][pg*16 + u*4 + 0] = __float2half_rn(v.x);
            t[cl][pg*16 + u*4 + 1] = __float2half_rn(v.y);
            t[cl][pg*16 + u*4 + 2] = __float2half_rn(v.z);
            t[cl][pg*16 + u*4 + 3] = __float2half_rn(v.w);
        }
        __syncthreads();
        int pl = tid >> 2;               // px row 0..63
        int cg = tid & 3;                // 16 c each
        __half* dst = g_xh + ((size_t)b*HW + pxt + pl)*CC_ + ct + cg*16;
        uint32_t buf[8];
        #pragma unroll
        for (int u = 0; u < 8; ++u) {
            __half lo = t[cg*16 + u*2][pl];
            __half hi = t[cg*16 + u*2 + 1][pl];
            buf[u] = ((uint32_t)__half_as_ushort(hi) << 16) | __half_as_ushort(lo);
        }
        uint4* d4 = (uint4*)dst;
        d4[0] = make_uint4(buf[0], buf[1], buf[2], buf[3]);
        d4[1] = make_uint4(buf[4], buf[5], buf[6], buf[7]);
    } else {
        // ---- dynw part: fp16 weights, layout [b][tap][oc][c] ----
        int idx = (bid - XCVT_BLOCKS) * 256 + tid;     // < 9,437,184
        int c2  = idx & 127;
        int r   = idx >> 7;
        int o   = r & 255;
        int r2  = r >> 8;
        int tap = r2 % 9;
        int b   = r2 / 9;
        int c0  = c2 * 2;

        const float4* kp = (const float4*)(g_kern + b*(CC_*CHK) + c0*CHK);
        float4 ka = kp[0];
        float4 kb = kp[1];
        float cg0 = cog[(o*CHK + 0)*9 + tap];
        float cg1 = cog[(o*CHK + 1)*9 + tap];
        float cg2 = cog[(o*CHK + 2)*9 + tap];
        float cg3 = cog[(o*CHK + 3)*9 + tap];
        float cw0 = ka.x*cg0 + ka.y*cg1 + ka.z*cg2 + ka.w*cg3;
        float cw1 = kb.x*cg0 + kb.y*cg1 + kb.z*cg2 + kb.w*cg3;
        float w0 = weight[((size_t)o*CC_ + c0)*9 + tap];
        float w1 = weight[((size_t)o*CC_ + c0 + 1)*9 + tap];
        float v0 = __fdividef(1.0f, 1.0f + __expf(-cw0)) * w0;
        float v1 = __fdividef(1.0f, 1.0f + __expf(-cw1)) * w1;

        __half h0 = __float2half_rn(v0);
        __half h1 = __float2half_rn(v1);
        g_w[idx] = ((uint32_t)__half_as_ushort(h1) << 16) | __half_as_ushort(h0);
    }
}

// ---------------- kernel 4: fp16 mma.sync implicit-GEMM conv (3-stage) ----------------
// Grid (25 px-tiles, 2 oc-halves, 32 b). Block 256 thr = 8 warps.
// Block tile 128 px x 128 oc; warp tile 64 px x 32 oc. K = 9 taps x 4 chunks x 64 c.
#define AB_BYTES 16384                 // 128 rows x 128B
#define NSTAGE 3
#define CONV_SMEM (2*NSTAGE*AB_BYTES)  // A0..A2,B0..B2 = 96KB

__global__ __launch_bounds__(256, 2)
void conv_mma(float* __restrict__ out) {
    extern __shared__ char smem[];
    const uint32_t sb = smem_u32(smem);
    const int tid = threadIdx.x;
    const int p0  = blockIdx.x * 128;
    const int ocb = blockIdx.y * 128;
    const int b   = blockIdx.z;

    // staging thread mapping: row r = tid>>1, half = tid&1 (4 x 16B units)
    const int sr   = tid >> 1;
    const int shalf= tid & 1;
    const int sp_  = p0 + sr;
    const int spy  = sp_ / WW;
    const int spx  = sp_ - spy * WW;
    const uint32_t sdst_row = sr*128 + shalf*64;
    const __half* xrow_base = g_xh + ((size_t)b*HW + sp_)*CC_;
    const uint32_t* wrow_base = g_w + ((size_t)(b*9))*OO*128 + (size_t)(ocb + sr)*128;

    auto stage = [&](int i) {
        int tap = i >> 2;        // 0..8
        int cch = i & 3;         // 0..3
        int st  = i % NSTAGE;
        int dy = tap/3 - 1, dx = tap%3 - 1;
        // A
        {
            bool valid = (sp_ < HW) && ((unsigned)(spy+dy) < HH) && ((unsigned)(spx+dx) < WW);
            uint32_t abuf = sb + st*AB_BYTES;
            const char* src = (const char*)(xrow_base + (dy*WW + dx)*CC_ + cch*64 + shalf*32);
            #pragma unroll
            for (int q = 0; q < 4; ++q) {
                uint32_t off = sdst_row + q*16;
                uint32_t dst = abuf + (off ^ ((off >> 3) & 0x70));
                if (valid) cp_async16(dst, src + q*16);
                else       st_smem_zero16(dst);
            }
        }
        // B
        {
            uint32_t bbuf = sb + NSTAGE*AB_BYTES + st*AB_BYTES;
            const char* src = (const char*)(wrow_base + (size_t)tap*OO*128 + cch*32 + shalf*16);
            #pragma unroll
            for (int q = 0; q < 4; ++q) {
                uint32_t off = sdst_row + q*16;
                uint32_t dst = bbuf + (off ^ ((off >> 3) & 0x70));
                cp_async16(dst, src + q*16);
            }
        }
        asm volatile("cp.async.commit_group;" ::: "memory");
    };

    // compute lane constants
    const int wid  = tid >> 5;
    const int lane = tid & 31;
    const int wm = (wid & 1) * 64;          // warp px offset
    const int wn = (wid >> 1) * 32;         // warp oc offset
    const uint32_t xm   = (uint32_t)(lane & 7) << 4;
    const uint32_t arow = (uint32_t)(wm + (lane & 15)) * 128;
    const uint32_t acol = (uint32_t)((lane >> 4) << 4);
    const uint32_t brow = (uint32_t)(wn + ((lane >> 4) << 3) + (lane & 7)) * 128;
    const uint32_t bcol = (uint32_t)(((lane >> 3) & 1) << 4);

    float d[16][4];
    #pragma unroll
    for (int i = 0; i < 16; ++i)
        #pragma unroll
        for (int k = 0; k < 4; ++k) d[i][k] = 0.f;

    stage(0);
    stage(1);

    for (int i = 0; i < 36; ++i) {
        // wait for stage i (allow 1 pending group = stage i+1; 0 at the end)
        if (i < 35) asm volatile("cp.async.wait_group 1;" ::: "memory");
        else        asm volatile("cp.async.wait_group 0;" ::: "memory");
        __syncthreads();
        // issue stage i+2 into buffer (i+2)%3 = (i-1)%3 — freed by the sync above
        if (i + 2 < 36) stage(i + 2);

        const int st = i % NSTAGE;
        const uint32_t abuf = sb + st*AB_BYTES;
        const uint32_t bbuf = sb + NSTAGE*AB_BYTES + st*AB_BYTES;
        #pragma unroll
        for (int ks = 0; ks < 4; ++ks) {
            uint32_t bfr[2][4];
            uint32_t bco = (uint32_t)(ks*32 + bcol) ^ xm;
            ldm4(bfr[0], bbuf + brow + bco);
            ldm4(bfr[1], bbuf + brow + 16*128 + bco);
            uint32_t aco = (uint32_t)(ks*32 + acol) ^ xm;
            #pragma unroll
            for (int mi = 0; mi < 4; ++mi) {
                uint32_t afr[4];
                ldm4(afr, abuf + arow + (uint32_t)mi*2048 + aco);
                mma16816(d[mi*4 + 0], afr, bfr[0][0], bfr[0][1]);
                mma16816(d[mi*4 + 1], afr, bfr[0][2], bfr[0][3]);
                mma16816(d[mi*4 + 2], afr, bfr[1][0], bfr[1][1]);
                mma16816(d[mi*4 + 3], afr, bfr[1][2], bfr[1][3]);
            }
        }
    }

    // epilogue
    const int t4 = lane >> 2;        // 0..7
    const int tm = lane & 3;         // 0..3
    #pragma unroll
    for (int mi = 0; mi < 4; ++mi) {
        int r0 = p0 + wm + mi*16 + t4;
        int r1 = r0 + 8;
        bool v0 = r0 < HW, v1 = r1 < HW;
        #pragma unroll
        for (int ni = 0; ni < 4; ++ni) {
            int oc = ocb + wn + ni*8 + tm*2;
            float* o0 = out + ((size_t)(b*OO + oc))*HW;
            float* o1 = o0 + HW;
            const float* dd = d[mi*4 + ni];
            if (v0) { o0[r0] = dd[0]; o1[r0] = dd[1]; }
            if (v1) { o0[r1] = dd[2]; o1[r1] = dd[3]; }
        }
    }
}

// ---------------- launcher ----------------
extern "C" void kernel_launch(void* const* d_in, const int* in_sizes, int n_in,
                              void* d_out, int out_size) {
    const float* x     = (const float*)d_in[0];
    const float* fc1_w = (const float*)d_in[1];
    const float* fc2_w = (const float*)d_in[2];
    const float* fc2_b = (const float*)d_in[3];
    const float* cog   = (const float*)d_in[4];
    const float* weight= (const float*)d_in[5];
    float* out = (float*)d_out;

    pool_kernel<<<BB*CC_, 128>>>(x);                       // launch 0
    fc12_kernel<<<BB, 1024>>>(fc1_w, fc2_w, fc2_b);        // launch 1
    combo_kernel<<<XCVT_BLOCKS + DYNW_BLOCKS, 256>>>(x, cog, weight);  // launch 2
    cudaFuncSetAttribute(conv_mma, cudaFuncAttributeMaxDynamicSharedMemorySize, CONV_SMEM);
    dim3 grid((HW + 127)/128, OO/128, BB);   // 25 x 2 x 32
    conv_mma<<<grid, 256, CONV_SMEM>>>(out);               // launch 3 -> profiled
}